// round 5
// baseline (speedup 1.0000x reference)
#include <cuda_runtime.h>
#include <cuda_bf16.h>
#include <cstdint>

#define B_ 2
#define L_ 64
#define D_ 1024
#define H_ 512
#define S_ 50000
#define V_ 40000
#define KDEG 32
#define R_ 128
#define BN_EPS 1e-5f
#define SLM_SCALE 0.1f

// ---- scratch (device globals; no allocation allowed) ----
__device__ float g_scale[L_];
__device__ float g_shift[L_];
__device__ __nv_bfloat16 g_h_hi[R_ * H_];
__device__ __nv_bfloat16 g_h_lo[R_ * H_];
__device__ __nv_bfloat16 g_vT[(size_t)V_ * R_];   // transposed v (bf16): [V][128]

// ============================================================
// helpers
// ============================================================
__device__ __forceinline__ uint32_t smem_u32(const void* p) {
    uint32_t a;
    asm("{ .reg .u64 t; cvta.to.shared.u64 t, %1; cvt.u32.u64 %0, t; }" : "=r"(a) : "l"(p));
    return a;
}
__device__ __forceinline__ void ldsm_x4(uint32_t* r, uint32_t addr) {
    asm volatile("ldmatrix.sync.aligned.m8n8.x4.shared.b16 {%0,%1,%2,%3}, [%4];"
        : "=r"(r[0]), "=r"(r[1]), "=r"(r[2]), "=r"(r[3]) : "r"(addr));
}
__device__ __forceinline__ void ldsm_x4_t(uint32_t* r, uint32_t addr) {
    asm volatile("ldmatrix.sync.aligned.m8n8.x4.trans.shared.b16 {%0,%1,%2,%3}, [%4];"
        : "=r"(r[0]), "=r"(r[1]), "=r"(r[2]), "=r"(r[3]) : "r"(addr));
}
__device__ __forceinline__ void mma16816(float* c, const uint32_t* a, const uint32_t* b) {
    asm volatile("mma.sync.aligned.m16n8k16.row.col.f32.bf16.bf16.f32 "
        "{%0,%1,%2,%3}, {%4,%5,%6,%7}, {%8,%9}, {%0,%1,%2,%3};"
        : "+f"(c[0]), "+f"(c[1]), "+f"(c[2]), "+f"(c[3])
        : "r"(a[0]), "r"(a[1]), "r"(a[2]), "r"(a[3]), "r"(b[0]), "r"(b[1]));
}
__device__ __forceinline__ uint32_t pack_hi2(float x, float y) {
    __nv_bfloat16 hx = __float2bfloat16(x), hy = __float2bfloat16(y);
    return (uint32_t)__bfloat16_as_ushort(hx) | ((uint32_t)__bfloat16_as_ushort(hy) << 16);
}
__device__ __forceinline__ uint32_t pack_lo2(float x, float y) {
    __nv_bfloat16 hx = __float2bfloat16(x), hy = __float2bfloat16(y);
    __nv_bfloat16 lx = __float2bfloat16(x - __bfloat162float(hx));
    __nv_bfloat16 ly = __float2bfloat16(y - __bfloat162float(hy));
    return (uint32_t)__bfloat16_as_ushort(lx) | ((uint32_t)__bfloat16_as_ushort(ly) << 16);
}

// ============================================================
// Kernel 1: BatchNorm stats
// ============================================================
__global__ void bn_stats_kernel(const float* __restrict__ x,
                                const float* __restrict__ gamma,
                                const float* __restrict__ beta) {
    int l = blockIdx.x;
    int t = threadIdx.x;
    float s = 0.f, sq = 0.f;
    for (int b = 0; b < B_; b++) {
        const float* row = x + ((size_t)(b * L_ + l)) * D_;
        for (int d = t; d < D_; d += 256) {
            float v = row[d];
            s += v; sq += v * v;
        }
    }
    __shared__ float sh_s[256], sh_q[256];
    sh_s[t] = s; sh_q[t] = sq;
    __syncthreads();
    for (int off = 128; off > 0; off >>= 1) {
        if (t < off) { sh_s[t] += sh_s[t + off]; sh_q[t] += sh_q[t + off]; }
        __syncthreads();
    }
    if (t == 0) {
        float inv = 1.f / (float)(B_ * D_);
        float mean = sh_s[0] * inv;
        float var = sh_q[0] * inv - mean * mean;
        float sc = gamma[l] * rsqrtf(var + BN_EPS);
        g_scale[l] = sc;
        g_shift[l] = beta[l] - mean * sc;
    }
}

// ============================================================
// Kernel 2: h = relu(BN(x)@W1+b1), emitted as split bf16 (hi/lo)
// ============================================================
__global__ void h_kernel(const float* __restrict__ A,
                         const float* __restrict__ W,
                         const float* __restrict__ bias) {
    constexpr int K = D_, N = H_;
    constexpr int BK = 16, TM = 8, TN = 4;
    __shared__ float As[BK][128];
    __shared__ float Bs[BK][64];

    const int tid = threadIdx.x;
    const int n0 = blockIdx.x * 64;
    const int trow = tid & 15;
    const int tcol = tid >> 4;
    const int kq = tid & 3;
    const int mA = tid >> 2;
    const int nq = tid & 15;
    const int kB = tid >> 4;

    float acc[TM][TN];
#pragma unroll
    for (int i = 0; i < TM; i++)
#pragma unroll
        for (int j = 0; j < TN; j++) acc[i][j] = 0.f;

    for (int k0 = 0; k0 < K; k0 += BK) {
#pragma unroll
        for (int mm = 0; mm < 2; mm++) {
            int m = mA + mm * 64;
            float4 a = *(const float4*)(A + (size_t)m * K + k0 + kq * 4);
            float sc = g_scale[m & (L_ - 1)];
            float sh = g_shift[m & (L_ - 1)];
            a.x = fmaf(a.x, sc, sh); a.y = fmaf(a.y, sc, sh);
            a.z = fmaf(a.z, sc, sh); a.w = fmaf(a.w, sc, sh);
            As[kq * 4 + 0][m] = a.x; As[kq * 4 + 1][m] = a.y;
            As[kq * 4 + 2][m] = a.z; As[kq * 4 + 3][m] = a.w;
        }
        {
            int n = n0 + nq * 4;
            float4 b = *(const float4*)(W + (size_t)(k0 + kB) * N + n);
            *(float4*)&Bs[kB][nq * 4] = b;
        }
        __syncthreads();
#pragma unroll
        for (int k = 0; k < BK; k++) {
            float a[TM], bb[TN];
#pragma unroll
            for (int i = 0; i < TM; i++) a[i] = As[k][trow * TM + i];
#pragma unroll
            for (int j = 0; j < TN; j++) bb[j] = Bs[k][tcol * TN + j];
#pragma unroll
            for (int i = 0; i < TM; i++)
#pragma unroll
                for (int j = 0; j < TN; j++) acc[i][j] = fmaf(a[i], bb[j], acc[i][j]);
        }
        __syncthreads();
    }

#pragma unroll
    for (int j = 0; j < TN; j++) {
        int n = n0 + tcol * TN + j;
        float bz = bias[n];
#pragma unroll
        for (int i = 0; i < TM; i++) {
            int m = trow * TM + i;
            float val = fmaxf(acc[i][j] + bz, 0.f);
            __nv_bfloat16 hi = __float2bfloat16(val);
            g_h_hi[(size_t)m * H_ + n] = hi;
            g_h_lo[(size_t)m * H_ + n] = __float2bfloat16(val - __bfloat162float(hi));
        }
    }
}

// ============================================================
// Kernel 3: pipelined split-bf16 mma.sync GEMM
//   C[128,N] = h[128,512] @ W[512,N] + bias
// MODE 1: out row-major [128][N] fp32 (y)
// MODE 2: out = g_vT transposed [N][128] bf16
// 2-stage cp.async pipeline: A direct bf16, W staged fp32 then converted.
// ============================================================
#define A_HI 0
#define A_LO 16384
#define B_HI 32768
#define B_LO 49152
#define B_STG 65536
#define PB_STRIDE 98304
#define GEMM_SMEM 196608

__device__ __forceinline__ void issue_chunk(uint32_t sb, const float* __restrict__ W,
                                            int N, int n0, int k0, int buf, int tid) {
    uint32_t base = sb + buf * PB_STRIDE;
    // A chunk: 128m x 64k bf16 hi/lo, swizzled 128B rows
#pragma unroll
    for (int i = 0; i < 4; i++) {
        int idx = i * 256 + tid;
        int m = idx >> 3, q = idx & 7;
        uint32_t off = (uint32_t)(m * 128 + ((q * 16) ^ ((m & 7) << 4)));
        const void* sh = g_h_hi + (size_t)m * H_ + k0 + q * 8;
        const void* sl = g_h_lo + (size_t)m * H_ + k0 + q * 8;
        asm volatile("cp.async.ca.shared.global [%0], [%1], 16;"
            :: "r"(base + A_HI + off), "l"(sh));
        asm volatile("cp.async.ca.shared.global [%0], [%1], 16;"
            :: "r"(base + A_LO + off), "l"(sl));
    }
    // B stage: 64k x 128n fp32, linear rows of 512B
#pragma unroll
    for (int i = 0; i < 8; i++) {
        int k = (tid >> 5) + i * 8;
        int nl = (tid & 31) * 4;
        int gn = n0 + nl;
        const float* src = (gn < N) ? (W + (size_t)(k0 + k) * N + gn) : W;
        uint32_t dst = base + B_STG + (uint32_t)(k * 512 + nl * 4);
        uint32_t sz = (gn < N) ? 16u : 0u;
        asm volatile("cp.async.ca.shared.global [%0], [%1], 16, %2;"
            :: "r"(dst), "l"(src), "r"(sz));
    }
    asm volatile("cp.async.commit_group;" ::: "memory");
}

template <int MODE>
__global__ void __launch_bounds__(256)
mma_gemm(const float* __restrict__ W, const float* __restrict__ bias,
         float* __restrict__ outparam, int N) {
    extern __shared__ char smem[];
    const uint32_t sb = smem_u32(smem);
    const int tid = threadIdx.x;
    const int lane = tid & 31;
    const int wid = tid >> 5;
    const int wm = wid >> 2;         // 0..1
    const int wn = wid & 3;          // 0..3
    const int n0 = blockIdx.x * 128;

    const int tt = lane >> 3;        // ldmatrix tile group 0..3
    const int lr = lane & 7;
    const uint32_t swz = (uint32_t)lr << 4;

    float c[4][4][4];
#pragma unroll
    for (int a = 0; a < 4; a++)
#pragma unroll
        for (int b = 0; b < 4; b++)
#pragma unroll
            for (int d = 0; d < 4; d++) c[a][b][d] = 0.f;

    // prologue: chunks 0, 1
    issue_chunk(sb, W, N, n0, 0, 0, tid);
    issue_chunk(sb, W, N, n0, 64, 1, tid);

    for (int ch = 0; ch < 8; ch++) {
        const int buf = ch & 1;
        const uint32_t base32 = (uint32_t)(buf * PB_STRIDE);
        char* cbase = smem + buf * PB_STRIDE;

        if (ch < 7) asm volatile("cp.async.wait_group 1;" ::: "memory");
        else        asm volatile("cp.async.wait_group 0;" ::: "memory");
        __syncthreads();

        // convert B stage fp32 -> bf16 hi/lo swizzled (256B rows, swz (k&7)<<4)
#pragma unroll
        for (int i = 0; i < 8; i++) {
            int k = (tid >> 5) + i * 8;
            int nl = (tid & 31) * 4;
            float4 w4 = *(const float4*)(cbase + B_STG + k * 512 + nl * 4);
            uint32_t off = (uint32_t)(k * 256 + ((nl * 2) ^ ((k & 7) << 4)));
            uint2 hv, lv;
            hv.x = pack_hi2(w4.x, w4.y); hv.y = pack_hi2(w4.z, w4.w);
            lv.x = pack_lo2(w4.x, w4.y); lv.y = pack_lo2(w4.z, w4.w);
            *(uint2*)(cbase + B_HI + off) = hv;
            *(uint2*)(cbase + B_LO + off) = lv;
        }
        __syncthreads();

        // consume: 4 k-steps of 16
#pragma unroll
        for (int ks = 0; ks < 4; ks++) {
            uint32_t bh[2][4], bl[2][4];
#pragma unroll
            for (int nt = 0; nt < 2; nt++) {
                uint32_t boff = base32 + B_HI + (uint32_t)((ks * 16 + (tt & 1) * 8 + lr) * 256 +
                                ((wn * 64 + nt * 32 + (tt >> 1) * 16) ^ swz));
                ldsm_x4_t(bh[nt], sb + boff);
                ldsm_x4_t(bl[nt], sb + boff + (B_LO - B_HI));
            }
#pragma unroll
            for (int mt = 0; mt < 4; mt++) {
                uint32_t ah[4], al[4];
                uint32_t aoff = base32 + A_HI + (uint32_t)((wm * 64 + mt * 16 + (tt & 1) * 8 + lr) * 128 +
                                ((ks * 32 + (tt >> 1) * 16) ^ swz));
                ldsm_x4(ah, sb + aoff);
                ldsm_x4(al, sb + aoff + (A_LO - A_HI));
#pragma unroll
                for (int nt = 0; nt < 2; nt++) {
#pragma unroll
                    for (int f = 0; f < 2; f++) {
                        float* cc = c[mt][nt * 2 + f];
                        mma16816(cc, ah, &bh[nt][2 * f]);
                        mma16816(cc, ah, &bl[nt][2 * f]);
                        mma16816(cc, al, &bh[nt][2 * f]);
                    }
                }
            }
        }
        __syncthreads();

        if (ch + 2 < 8) issue_chunk(sb, W, N, n0, (ch + 2) * 64, buf, tid);
    }

    // ---- epilogue ----
    if (MODE == 1) {
        float* out = outparam;
#pragma unroll
        for (int mt = 0; mt < 4; mt++) {
            int m = wm * 64 + mt * 16 + (lane >> 2);
#pragma unroll
            for (int nt = 0; nt < 4; nt++) {
                int gn = n0 + wn * 32 + nt * 8 + 2 * (lane & 3);
                if (gn < N) {
                    float b0 = __ldg(bias + gn), b1 = __ldg(bias + gn + 1);
                    float2 v0 = make_float2(c[mt][nt][0] + b0, c[mt][nt][1] + b1);
                    float2 v1 = make_float2(c[mt][nt][2] + b0, c[mt][nt][3] + b1);
                    *(float2*)(out + (size_t)m * N + gn) = v0;
                    *(float2*)(out + (size_t)(m + 8) * N + gn) = v1;
                }
            }
        }
    } else {
        // stage to smem, then write transposed bf16 rows coalesced
        float* sf = (float*)smem;   // [128 m][132]
#pragma unroll
        for (int mt = 0; mt < 4; mt++) {
            int m = wm * 64 + mt * 16 + (lane >> 2);
#pragma unroll
            for (int nt = 0; nt < 4; nt++) {
                int nl = wn * 32 + nt * 8 + 2 * (lane & 3);
                int gn = n0 + nl;
                float b0 = (gn < N) ? __ldg(bias + gn) : 0.f;
                float b1 = (gn + 1 < N) ? __ldg(bias + gn + 1) : 0.f;
                *(float2*)(sf + m * 132 + nl) = make_float2(c[mt][nt][0] + b0, c[mt][nt][1] + b1);
                *(float2*)(sf + (m + 8) * 132 + nl) = make_float2(c[mt][nt][2] + b0, c[mt][nt][3] + b1);
            }
        }
        __syncthreads();
        for (int idx = tid; idx < 128 * 64; idx += 256) {
            int n = idx >> 6, mp = idx & 63;
            int gn = n0 + n;
            if (gn < N) {
                float v0 = sf[(2 * mp) * 132 + n];
                float v1 = sf[(2 * mp + 1) * 132 + n];
                uint32_t packed = pack_hi2(v0, v1);
                *(uint32_t*)((char*)g_vT + ((size_t)gn * R_ + 2 * mp) * 2) = packed;
            }
        }
    }
}

// ============================================================
// Kernel 4: sparse gather-sum (bf16 vT) + scaled add into y
// ============================================================
__global__ void gather_kernel(const int* __restrict__ sl_idx,
                              const float* __restrict__ sl_w,
                              float* __restrict__ out) {
    constexpr int TS = 64;
    __shared__ float tile[R_][TS + 1];
    int s0 = blockIdx.x * TS;
    int wid = threadIdx.x >> 5;
    int lane = threadIdx.x & 31;

    for (int sl = wid; sl < TS; sl += 8) {
        int s = s0 + sl;
        float4 acc = make_float4(0.f, 0.f, 0.f, 0.f);
        if (s < S_) {
            int j = sl_idx[(size_t)s * KDEG + lane];
            float wk = sl_w[(size_t)s * KDEG + lane];
#pragma unroll
            for (int k = 0; k < KDEG; k++) {
                int jj = __shfl_sync(0xffffffffu, j, k);
                float wkk = __shfl_sync(0xffffffffu, wk, k);
                uint2 raw = *(const uint2*)(g_vT + (size_t)jj * R_ + lane * 4);
                __nv_bfloat162 p0 = *reinterpret_cast<__nv_bfloat162*>(&raw.x);
                __nv_bfloat162 p1 = *reinterpret_cast<__nv_bfloat162*>(&raw.y);
                float2 f0 = __bfloat1622float2(p0);
                float2 f1 = __bfloat1622float2(p1);
                acc.x = fmaf(wkk, f0.x, acc.x);
                acc.y = fmaf(wkk, f0.y, acc.y);
                acc.z = fmaf(wkk, f1.x, acc.z);
                acc.w = fmaf(wkk, f1.y, acc.w);
            }
        }
        tile[lane * 4 + 0][sl] = acc.x;
        tile[lane * 4 + 1][sl] = acc.y;
        tile[lane * 4 + 2][sl] = acc.z;
        tile[lane * 4 + 3][sl] = acc.w;
    }
    __syncthreads();

    int nvalid = S_ - s0;
    if (nvalid > TS) nvalid = TS;
    for (int it = threadIdx.x; it < R_ * TS; it += 256) {
        int sl = it & (TS - 1);
        int row = it >> 6;
        if (sl < nvalid) {
            size_t o = (size_t)row * S_ + s0 + sl;
            out[o] += SLM_SCALE * tile[row][sl];
        }
    }
}

// ============================================================
extern "C" void kernel_launch(void* const* d_in, const int* in_sizes, int n_in,
                              void* d_out, int out_size) {
    const float* x     = (const float*)d_in[0];
    const float* gamma = (const float*)d_in[1];
    const float* beta  = (const float*)d_in[2];
    const float* W1    = (const float*)d_in[3];
    const float* b1    = (const float*)d_in[4];
    const float* W2    = (const float*)d_in[5];
    const float* b2    = (const float*)d_in[6];
    const float* Wslm  = (const float*)d_in[7];
    const float* bslm  = (const float*)d_in[8];
    const float* slw   = (const float*)d_in[9];
    const int*   slidx = (const int*)d_in[10];
    float* out = (float*)d_out;

    cudaFuncSetAttribute(mma_gemm<1>, cudaFuncAttributeMaxDynamicSharedMemorySize, GEMM_SMEM);
    cudaFuncSetAttribute(mma_gemm<2>, cudaFuncAttributeMaxDynamicSharedMemorySize, GEMM_SMEM);

    bn_stats_kernel<<<L_, 256>>>(x, gamma, beta);
    h_kernel<<<H_ / 64, 256>>>(x, W1, b1);
    mma_gemm<1><<<(S_ + 127) / 128, 256, GEMM_SMEM>>>(W2, b2, out, S_);
    mma_gemm<2><<<(V_ + 127) / 128, 256, GEMM_SMEM>>>(Wslm, bslm, nullptr, V_);
    gather_kernel<<<(S_ + 63) / 64, 256>>>(slidx, slw, out);
}

// round 6
// speedup vs baseline: 1.3350x; 1.3350x over previous
#include <cuda_runtime.h>
#include <cuda_bf16.h>
#include <cstdint>

#define B_ 2
#define L_ 64
#define D_ 1024
#define H_ 512
#define S_ 50000
#define V_ 40000
#define KDEG 32
#define R_ 128
#define BN_EPS 1e-5f
#define SLM_SCALE 0.1f

// ---- scratch (device globals; no allocation allowed) ----
__device__ float g_scale[L_];
__device__ float g_shift[L_];
__device__ __nv_bfloat16 g_h_hi[R_ * H_];
__device__ __nv_bfloat16 g_h_lo[R_ * H_];
__device__ __nv_bfloat16 g_vT[(size_t)V_ * R_];   // transposed v (bf16): [V][128]

// ============================================================
// helpers
// ============================================================
__device__ __forceinline__ uint32_t smem_u32(const void* p) {
    uint32_t a;
    asm("{ .reg .u64 t; cvta.to.shared.u64 t, %1; cvt.u32.u64 %0, t; }" : "=r"(a) : "l"(p));
    return a;
}
__device__ __forceinline__ void ldsm_x4(uint32_t* r, uint32_t addr) {
    asm volatile("ldmatrix.sync.aligned.m8n8.x4.shared.b16 {%0,%1,%2,%3}, [%4];"
        : "=r"(r[0]), "=r"(r[1]), "=r"(r[2]), "=r"(r[3]) : "r"(addr));
}
__device__ __forceinline__ void ldsm_x4_t(uint32_t* r, uint32_t addr) {
    asm volatile("ldmatrix.sync.aligned.m8n8.x4.trans.shared.b16 {%0,%1,%2,%3}, [%4];"
        : "=r"(r[0]), "=r"(r[1]), "=r"(r[2]), "=r"(r[3]) : "r"(addr));
}
__device__ __forceinline__ void mma16816(float* c, const uint32_t* a, const uint32_t* b) {
    asm volatile("mma.sync.aligned.m16n8k16.row.col.f32.bf16.bf16.f32 "
        "{%0,%1,%2,%3}, {%4,%5,%6,%7}, {%8,%9}, {%0,%1,%2,%3};"
        : "+f"(c[0]), "+f"(c[1]), "+f"(c[2]), "+f"(c[3])
        : "r"(a[0]), "r"(a[1]), "r"(a[2]), "r"(a[3]), "r"(b[0]), "r"(b[1]));
}
__device__ __forceinline__ uint32_t pack_hi2(float x, float y) {
    __nv_bfloat16 hx = __float2bfloat16(x), hy = __float2bfloat16(y);
    return (uint32_t)__bfloat16_as_ushort(hx) | ((uint32_t)__bfloat16_as_ushort(hy) << 16);
}
__device__ __forceinline__ uint32_t pack_lo2(float x, float y) {
    __nv_bfloat16 hx = __float2bfloat16(x), hy = __float2bfloat16(y);
    __nv_bfloat16 lx = __float2bfloat16(x - __bfloat162float(hx));
    __nv_bfloat16 ly = __float2bfloat16(y - __bfloat162float(hy));
    return (uint32_t)__bfloat16_as_ushort(lx) | ((uint32_t)__bfloat16_as_ushort(ly) << 16);
}

// ============================================================
// Kernel 1: BatchNorm stats
// ============================================================
__global__ void bn_stats_kernel(const float* __restrict__ x,
                                const float* __restrict__ gamma,
                                const float* __restrict__ beta) {
    int l = blockIdx.x;
    int t = threadIdx.x;
    float s = 0.f, sq = 0.f;
    for (int b = 0; b < B_; b++) {
        const float* row = x + ((size_t)(b * L_ + l)) * D_;
        for (int d = t; d < D_; d += 256) {
            float v = row[d];
            s += v; sq += v * v;
        }
    }
    __shared__ float sh_s[256], sh_q[256];
    sh_s[t] = s; sh_q[t] = sq;
    __syncthreads();
    for (int off = 128; off > 0; off >>= 1) {
        if (t < off) { sh_s[t] += sh_s[t + off]; sh_q[t] += sh_q[t + off]; }
        __syncthreads();
    }
    if (t == 0) {
        float inv = 1.f / (float)(B_ * D_);
        float mean = sh_s[0] * inv;
        float var = sh_q[0] * inv - mean * mean;
        float sc = gamma[l] * rsqrtf(var + BN_EPS);
        g_scale[l] = sc;
        g_shift[l] = beta[l] - mean * sc;
    }
}

// ============================================================
// Kernel 2: h = relu(BN(x)@W1+b1), emitted as split bf16 (hi/lo)
// ============================================================
__global__ void h_kernel(const float* __restrict__ A,
                         const float* __restrict__ W,
                         const float* __restrict__ bias) {
    constexpr int K = D_, N = H_;
    constexpr int BK = 16, TM = 8, TN = 4;
    __shared__ float As[BK][128];
    __shared__ float Bs[BK][64];

    const int tid = threadIdx.x;
    const int n0 = blockIdx.x * 64;
    const int trow = tid & 15;
    const int tcol = tid >> 4;
    const int kq = tid & 3;
    const int mA = tid >> 2;
    const int nq = tid & 15;
    const int kB = tid >> 4;

    float acc[TM][TN];
#pragma unroll
    for (int i = 0; i < TM; i++)
#pragma unroll
        for (int j = 0; j < TN; j++) acc[i][j] = 0.f;

    for (int k0 = 0; k0 < K; k0 += BK) {
#pragma unroll
        for (int mm = 0; mm < 2; mm++) {
            int m = mA + mm * 64;
            float4 a = *(const float4*)(A + (size_t)m * K + k0 + kq * 4);
            float sc = g_scale[m & (L_ - 1)];
            float sh = g_shift[m & (L_ - 1)];
            a.x = fmaf(a.x, sc, sh); a.y = fmaf(a.y, sc, sh);
            a.z = fmaf(a.z, sc, sh); a.w = fmaf(a.w, sc, sh);
            As[kq * 4 + 0][m] = a.x; As[kq * 4 + 1][m] = a.y;
            As[kq * 4 + 2][m] = a.z; As[kq * 4 + 3][m] = a.w;
        }
        {
            int n = n0 + nq * 4;
            float4 b = *(const float4*)(W + (size_t)(k0 + kB) * N + n);
            *(float4*)&Bs[kB][nq * 4] = b;
        }
        __syncthreads();
#pragma unroll
        for (int k = 0; k < BK; k++) {
            float a[TM], bb[TN];
#pragma unroll
            for (int i = 0; i < TM; i++) a[i] = As[k][trow * TM + i];
#pragma unroll
            for (int j = 0; j < TN; j++) bb[j] = Bs[k][tcol * TN + j];
#pragma unroll
            for (int i = 0; i < TM; i++)
#pragma unroll
                for (int j = 0; j < TN; j++) acc[i][j] = fmaf(a[i], bb[j], acc[i][j]);
        }
        __syncthreads();
    }

#pragma unroll
    for (int j = 0; j < TN; j++) {
        int n = n0 + tcol * TN + j;
        float bz = bias[n];
#pragma unroll
        for (int i = 0; i < TM; i++) {
            int m = trow * TM + i;
            float val = fmaxf(acc[i][j] + bz, 0.f);
            __nv_bfloat16 hi = __float2bfloat16(val);
            g_h_hi[(size_t)m * H_ + n] = hi;
            g_h_lo[(size_t)m * H_ + n] = __float2bfloat16(val - __bfloat162float(hi));
        }
    }
}

// ============================================================
// Kernel 3: split-bf16 mma.sync GEMM  C[128,N] = h[128,512]@W[512,N] + bias
// MODE 1: out row-major [128][N] fp32 (y)
// MODE 2: out = g_vT transposed [N][128] bf16
// CTA: 256 threads (8 warps, 2M x 4N), tile 128x128, K chunks of 64.
// __launch_bounds__(256,2): 2 CTAs/SM for cross-CTA phase overlap.
// ============================================================
#define A_HI 0
#define A_LO 16384
#define B_HI 32768
#define B_LO 49152
#define GEMM_SMEM 67584   // max(stage 64KB, epilogue 128*132*4)

template <int MODE>
__global__ void __launch_bounds__(256, 2)
mma_gemm(const float* __restrict__ W, const float* __restrict__ bias,
         float* __restrict__ outparam, int N) {
    extern __shared__ char smem[];
    const uint32_t sb = smem_u32(smem);
    const int tid = threadIdx.x;
    const int lane = tid & 31;
    const int wid = tid >> 5;
    const int wm = wid >> 2;         // 0..1
    const int wn = wid & 3;          // 0..3
    const int n0 = blockIdx.x * 128;

    const int tt = lane >> 3;        // ldmatrix tile group 0..3
    const int lr = lane & 7;
    const uint32_t swz = (uint32_t)lr << 4;

    float c[4][4][4];
#pragma unroll
    for (int a = 0; a < 4; a++)
#pragma unroll
        for (int b = 0; b < 4; b++)
#pragma unroll
            for (int d = 0; d < 4; d++) c[a][b][d] = 0.f;

    for (int ch = 0; ch < 8; ch++) {
        const int k0 = ch * 64;

        // ---- fill A: [128 m][64 k] bf16 hi/lo, swizzled 128B rows
#pragma unroll
        for (int i = 0; i < 4; i++) {
            int idx = i * 256 + tid;
            int m = idx >> 3, q = idx & 7;
            uint32_t off = (uint32_t)(m * 128 + ((q * 16) ^ ((m & 7) << 4)));
            *(uint4*)(smem + A_HI + off) = *(const uint4*)(g_h_hi + (size_t)m * H_ + k0 + q * 8);
            *(uint4*)(smem + A_LO + off) = *(const uint4*)(g_h_lo + (size_t)m * H_ + k0 + q * 8);
        }
        // ---- fill B: [64 k][128 n] bf16 hi/lo, rows 256B, swizzle ((k&7)<<4)
#pragma unroll
        for (int i = 0; i < 8; i++) {
            int k = (tid >> 5) + i * 8;
            int nl = (tid & 31) * 4;
            int gn = n0 + nl;
            float4 w4 = make_float4(0.f, 0.f, 0.f, 0.f);
            if (gn < N) w4 = *(const float4*)(W + (size_t)(k0 + k) * N + gn);
            uint32_t off = (uint32_t)(k * 256 + ((nl * 2) ^ ((k & 7) << 4)));
            uint2 hv, lv;
            hv.x = pack_hi2(w4.x, w4.y); hv.y = pack_hi2(w4.z, w4.w);
            lv.x = pack_lo2(w4.x, w4.y); lv.y = pack_lo2(w4.z, w4.w);
            *(uint2*)(smem + B_HI + off) = hv;
            *(uint2*)(smem + B_LO + off) = lv;
        }
        __syncthreads();

        // ---- consume: 4 k-steps of 16
#pragma unroll
        for (int ks = 0; ks < 4; ks++) {
            uint32_t bh[2][4], bl[2][4];
#pragma unroll
            for (int nt = 0; nt < 2; nt++) {
                uint32_t boff = (uint32_t)((ks * 16 + (tt & 1) * 8 + lr) * 256 +
                                ((wn * 64 + nt * 32 + (tt >> 1) * 16) ^ swz));
                ldsm_x4_t(bh[nt], sb + B_HI + boff);
                ldsm_x4_t(bl[nt], sb + B_LO + boff);
            }
#pragma unroll
            for (int mt = 0; mt < 4; mt++) {
                uint32_t ah[4], al[4];
                uint32_t aoff = (uint32_t)((wm * 64 + mt * 16 + (tt & 1) * 8 + lr) * 128 +
                                ((ks * 32 + (tt >> 1) * 16) ^ swz));
                ldsm_x4(ah, sb + A_HI + aoff);
                ldsm_x4(al, sb + A_LO + aoff);
#pragma unroll
                for (int nt = 0; nt < 2; nt++) {
#pragma unroll
                    for (int f = 0; f < 2; f++) {
                        float* cc = c[mt][nt * 2 + f];
                        mma16816(cc, ah, &bh[nt][2 * f]);
                        mma16816(cc, ah, &bl[nt][2 * f]);
                        mma16816(cc, al, &bh[nt][2 * f]);
                    }
                }
            }
        }
        __syncthreads();
    }

    // ---- epilogue ----
    if (MODE == 1) {
        float* out = outparam;
#pragma unroll
        for (int mt = 0; mt < 4; mt++) {
            int m = wm * 64 + mt * 16 + (lane >> 2);
#pragma unroll
            for (int nt = 0; nt < 4; nt++) {
                int gn = n0 + wn * 32 + nt * 8 + 2 * (lane & 3);
                if (gn < N) {
                    float b0 = __ldg(bias + gn), b1 = __ldg(bias + gn + 1);
                    float2 v0 = make_float2(c[mt][nt][0] + b0, c[mt][nt][1] + b1);
                    float2 v1 = make_float2(c[mt][nt][2] + b0, c[mt][nt][3] + b1);
                    *(float2*)(out + (size_t)m * N + gn) = v0;
                    *(float2*)(out + (size_t)(m + 8) * N + gn) = v1;
                }
            }
        }
    } else {
        // stage to smem, then write transposed bf16 rows coalesced
        float* sf = (float*)smem;   // [128 m][132]
#pragma unroll
        for (int mt = 0; mt < 4; mt++) {
            int m = wm * 64 + mt * 16 + (lane >> 2);
#pragma unroll
            for (int nt = 0; nt < 4; nt++) {
                int nl = wn * 32 + nt * 8 + 2 * (lane & 3);
                int gn = n0 + nl;
                float b0 = (gn < N) ? __ldg(bias + gn) : 0.f;
                float b1 = (gn + 1 < N) ? __ldg(bias + gn + 1) : 0.f;
                *(float2*)(sf + m * 132 + nl) = make_float2(c[mt][nt][0] + b0, c[mt][nt][1] + b1);
                *(float2*)(sf + (m + 8) * 132 + nl) = make_float2(c[mt][nt][2] + b0, c[mt][nt][3] + b1);
            }
        }
        __syncthreads();
        for (int idx = tid; idx < 128 * 64; idx += 256) {
            int n = idx >> 6, mp = idx & 63;
            int gn = n0 + n;
            if (gn < N) {
                float v0 = sf[(2 * mp) * 132 + n];
                float v1 = sf[(2 * mp + 1) * 132 + n];
                uint32_t packed = pack_hi2(v0, v1);
                *(uint32_t*)((char*)g_vT + ((size_t)gn * R_ + 2 * mp) * 2) = packed;
            }
        }
    }
}

// ============================================================
// Kernel 4: sparse gather-sum (bf16 vT) + scaled add into y
// (idx,w) pairs staged in smem -> no shuffles in the hot loop.
// ============================================================
#define GTS 64
#define GATHER_SMEM (GTS * KDEG * 8 + R_ * (GTS + 1) * 4)   // 16384 + 33280

__global__ void __launch_bounds__(256)
gather_kernel(const int* __restrict__ sl_idx,
              const float* __restrict__ sl_w,
              float* __restrict__ out) {
    extern __shared__ char gsm[];
    uint2* s_pair = (uint2*)gsm;                       // [GTS*KDEG]
    float* tile = (float*)(gsm + GTS * KDEG * 8);      // [R_][GTS+1]

    int s0 = blockIdx.x * GTS;
    int tid = threadIdx.x;
    int wid = tid >> 5;
    int lane = tid & 31;

    // stage (idx, weight) pairs, coalesced
#pragma unroll
    for (int i = 0; i < GTS * KDEG / 256; i++) {
        int e = i * 256 + tid;
        int gs = s0 * KDEG + e;
        uint2 p = make_uint2(0u, 0u);
        if (gs < S_ * KDEG) {
            p.x = (uint32_t)sl_idx[gs];
            p.y = __float_as_uint(sl_w[gs]);
        }
        s_pair[e] = p;
    }
    __syncthreads();

    for (int sl = wid; sl < GTS; sl += 8) {
        float4 acc = make_float4(0.f, 0.f, 0.f, 0.f);
#pragma unroll
        for (int k = 0; k < KDEG; k++) {
            uint2 p = s_pair[sl * KDEG + k];          // LDS.64 broadcast
            float wkk = __uint_as_float(p.y);
            uint2 raw = *(const uint2*)(g_vT + (size_t)p.x * R_ + lane * 4);
            __nv_bfloat162 p0 = *reinterpret_cast<__nv_bfloat162*>(&raw.x);
            __nv_bfloat162 p1 = *reinterpret_cast<__nv_bfloat162*>(&raw.y);
            float2 f0 = __bfloat1622float2(p0);
            float2 f1 = __bfloat1622float2(p1);
            acc.x = fmaf(wkk, f0.x, acc.x);
            acc.y = fmaf(wkk, f0.y, acc.y);
            acc.z = fmaf(wkk, f1.x, acc.z);
            acc.w = fmaf(wkk, f1.y, acc.w);
        }
        tile[(lane * 4 + 0) * (GTS + 1) + sl] = acc.x;
        tile[(lane * 4 + 1) * (GTS + 1) + sl] = acc.y;
        tile[(lane * 4 + 2) * (GTS + 1) + sl] = acc.z;
        tile[(lane * 4 + 3) * (GTS + 1) + sl] = acc.w;
    }
    __syncthreads();

    int nvalid = S_ - s0;
    if (nvalid > GTS) nvalid = GTS;
    for (int it = tid; it < R_ * GTS; it += 256) {
        int sl = it & (GTS - 1);
        int row = it >> 6;
        if (sl < nvalid) {
            size_t o = (size_t)row * S_ + s0 + sl;
            out[o] += SLM_SCALE * tile[row * (GTS + 1) + sl];
        }
    }
}

// ============================================================
extern "C" void kernel_launch(void* const* d_in, const int* in_sizes, int n_in,
                              void* d_out, int out_size) {
    const float* x     = (const float*)d_in[0];
    const float* gamma = (const float*)d_in[1];
    const float* beta  = (const float*)d_in[2];
    const float* W1    = (const float*)d_in[3];
    const float* b1    = (const float*)d_in[4];
    const float* W2    = (const float*)d_in[5];
    const float* b2    = (const float*)d_in[6];
    const float* Wslm  = (const float*)d_in[7];
    const float* bslm  = (const float*)d_in[8];
    const float* slw   = (const float*)d_in[9];
    const int*   slidx = (const int*)d_in[10];
    float* out = (float*)d_out;

    cudaFuncSetAttribute(mma_gemm<1>, cudaFuncAttributeMaxDynamicSharedMemorySize, GEMM_SMEM);
    cudaFuncSetAttribute(mma_gemm<2>, cudaFuncAttributeMaxDynamicSharedMemorySize, GEMM_SMEM);
    cudaFuncSetAttribute(gather_kernel, cudaFuncAttributeMaxDynamicSharedMemorySize, GATHER_SMEM);

    bn_stats_kernel<<<L_, 256>>>(x, gamma, beta);
    h_kernel<<<H_ / 64, 256>>>(x, W1, b1);
    mma_gemm<1><<<(S_ + 127) / 128, 256, GEMM_SMEM>>>(W2, b2, out, S_);
    mma_gemm<2><<<(V_ + 127) / 128, 256, GEMM_SMEM>>>(Wslm, bslm, nullptr, V_);
    gather_kernel<<<(S_ + 63) / 64, 256, GATHER_SMEM>>>(slidx, slw, out);
}